// round 7
// baseline (speedup 1.0000x reference)
#include <cuda_runtime.h>
#include <math.h>

#define BATCH 1024
#define INPUT_SIZE 512
#define HIDDEN 1024
#define N_QP 64
#define M_QP 128
#define QP_ITER 50
#define N_P 2080          // 64*65/2
#define N_HMAT 8192       // 128*64
#define N_OUT 10464       // 2080 + 64 + 8192 + 128
#define HOFF 2144         // N_P + N_QP
#define LTS 68            // sLT row stride (multiple of 4 for float4 alignment)

__device__ __align__(16) float g_h1[BATCH * HIDDEN];
__device__ __align__(16) float g_h2[BATCH * HIDDEN];
__device__ __align__(16) float g_out3[BATCH * N_OUT];

// ---------------------------------------------------------------------------
// Tiled fp32 SGEMM with fused bias (+ optional ReLU) — unchanged (fp32 peak)
// ---------------------------------------------------------------------------
template <bool RELU>
__global__ __launch_bounds__(256)
void sgemm_bias(const float* __restrict__ A, const float* __restrict__ B,
                const float* __restrict__ bias, float* __restrict__ C,
                int M, int N, int K)
{
    __shared__ float As[16 * 65];
    __shared__ float Bs[16 * 64];

    const int tid = threadIdx.x;
    const int tx = tid & 15;
    const int ty = tid >> 4;
    const int m0 = blockIdx.y * 64;
    const int n0 = blockIdx.x * 64;

    const int aRow = tid >> 2;
    const int aC4  = tid & 3;
    const int bRow = tid >> 4;
    const int bC4  = tid & 15;

    float acc[4][4] = {};

    for (int k0 = 0; k0 < K; k0 += 16) {
        float4 av = *(const float4*)&A[(size_t)(m0 + aRow) * K + k0 + aC4 * 4];
        int bn = n0 + bC4 * 4;
        float4 bv = make_float4(0.f, 0.f, 0.f, 0.f);
        if (bn < N) bv = *(const float4*)&B[(size_t)(k0 + bRow) * N + bn];

        __syncthreads();
        As[(aC4 * 4 + 0) * 65 + aRow] = av.x;
        As[(aC4 * 4 + 1) * 65 + aRow] = av.y;
        As[(aC4 * 4 + 2) * 65 + aRow] = av.z;
        As[(aC4 * 4 + 3) * 65 + aRow] = av.w;
        *(float4*)&Bs[bRow * 64 + bC4 * 4] = bv;
        __syncthreads();

        #pragma unroll
        for (int k = 0; k < 16; ++k) {
            float4 bb = *(const float4*)&Bs[k * 64 + tx * 4];
            float a0 = As[k * 65 + ty * 4 + 0];
            float a1 = As[k * 65 + ty * 4 + 1];
            float a2 = As[k * 65 + ty * 4 + 2];
            float a3 = As[k * 65 + ty * 4 + 3];
            acc[0][0] = fmaf(a0, bb.x, acc[0][0]);
            acc[0][1] = fmaf(a0, bb.y, acc[0][1]);
            acc[0][2] = fmaf(a0, bb.z, acc[0][2]);
            acc[0][3] = fmaf(a0, bb.w, acc[0][3]);
            acc[1][0] = fmaf(a1, bb.x, acc[1][0]);
            acc[1][1] = fmaf(a1, bb.y, acc[1][1]);
            acc[1][2] = fmaf(a1, bb.z, acc[1][2]);
            acc[1][3] = fmaf(a1, bb.w, acc[1][3]);
            acc[2][0] = fmaf(a2, bb.x, acc[2][0]);
            acc[2][1] = fmaf(a2, bb.y, acc[2][1]);
            acc[2][2] = fmaf(a2, bb.z, acc[2][2]);
            acc[2][3] = fmaf(a2, bb.w, acc[2][3]);
            acc[3][0] = fmaf(a3, bb.x, acc[3][0]);
            acc[3][1] = fmaf(a3, bb.y, acc[3][1]);
            acc[3][2] = fmaf(a3, bb.z, acc[3][2]);
            acc[3][3] = fmaf(a3, bb.w, acc[3][3]);
        }
    }

    #pragma unroll
    for (int ii = 0; ii < 4; ++ii) {
        int m = m0 + ty * 4 + ii;
        #pragma unroll
        for (int jj = 0; jj < 4; ++jj) {
            int n = n0 + tx * 4 + jj;
            if (n < N) {
                float v = acc[ii][jj] + bias[n];
                if (RELU) v = fmaxf(v, 0.f);
                C[(size_t)m * N + n] = v;
            }
        }
    }
}

// ---------------------------------------------------------------------------
// QP solver. 512 threads per CTA, one CTA per batch item.
//   rHr[16]: thread t holds H[r][16*h4+k],             r=t>>2, h4=t&3
//   rHc[16]: thread t holds H[16*g8+j][c],             c=t>>3, g8=t&7
//   rM [8] : thread t holds Minv[c][8*g8+j]
// ALL register-array indices are compile-time (no local-memory demotion).
// ---------------------------------------------------------------------------
__device__ __forceinline__ float sel8(const float* rm, int kj) {
    float v = rm[0];
    #pragma unroll
    for (int j = 1; j < 8; ++j) v = (j == kj) ? rm[j] : v;
    return v;
}

__global__ __launch_bounds__(512, 2)
void solver_kernel(const float* __restrict__ out3, float* __restrict__ xs)
{
    __shared__ __align__(16) float sLT[64 * LTS];  // H-stage buffer, then L^T
    __shared__ __align__(16) float spiv[2 * 64];
    __shared__ __align__(16) float sxbar[64];
    __shared__ __align__(16) float st[64];
    __shared__ __align__(16) float slam[128];
    __shared__ __align__(16) float sb[128];
    __shared__ __align__(16) float sq[64];
    __shared__ __align__(16) float sv[64];
    __shared__ __align__(16) float sw[128];
    __shared__ float spart[16];
    __shared__ float s_scal, s_tau;

    const int t    = threadIdx.x;
    const int lane = t & 31;
    const int warp = t >> 5;
    const int r    = t >> 2;   // 0..127
    const int h4   = t & 3;
    const int c    = t >> 3;   // 0..63
    const int g8   = t & 7;

    const float* row = out3 + (size_t)blockIdx.x * N_OUT;
    const unsigned FULL = 0xffffffffu;

    // ---- Load H row slices directly from gmem (coalesced float4) ----
    float rHr[16];
    {
        const float4* base = (const float4*)(row + HOFF + r * 64 + 16 * h4);
        float4 v0 = base[0], v1 = base[1], v2 = base[2], v3 = base[3];
        rHr[0]=v0.x; rHr[1]=v0.y; rHr[2]=v0.z; rHr[3]=v0.w;
        rHr[4]=v1.x; rHr[5]=v1.y; rHr[6]=v1.z; rHr[7]=v1.w;
        rHr[8]=v2.x; rHr[9]=v2.y; rHr[10]=v2.z; rHr[11]=v2.w;
        rHr[12]=v3.x; rHr[13]=v3.y; rHr[14]=v3.z; rHr[15]=v3.w;
    }

    // ---- Load H column slices via 2-chunk smem staging ----
    float rHc[16];
    {
        // chunk 0: rows 0..63
        const float4* src = (const float4*)(row + HOFF + (t >> 3) * 64 + 8 * (t & 7));
        float4 a = src[0], b = src[1];
        float* dst = &sLT[(t >> 3) * LTS + 8 * (t & 7)];
        *(float4*)dst = a; *(float4*)(dst + 4) = b;
    }
    __syncthreads();
    if (g8 < 4) {
        #pragma unroll
        for (int j = 0; j < 16; ++j) {
            int jj = (j + 2 * g8) & 15;                 // smem index only
            rHc[j] = sLT[(16 * g8 + jj) * LTS + c];     // wait: must match j->row
        }
        // NOTE: rHc[j] must hold H[16*g8 + j][c]; redo without rotation:
        #pragma unroll
        for (int j = 0; j < 16; ++j)
            rHc[j] = sLT[(16 * g8 + j) * LTS + c];
    }
    __syncthreads();
    {
        // chunk 1: rows 64..127
        const float4* src = (const float4*)(row + HOFF + (64 + (t >> 3)) * 64 + 8 * (t & 7));
        float4 a = src[0], b = src[1];
        float* dst = &sLT[(t >> 3) * LTS + 8 * (t & 7)];
        *(float4*)dst = a; *(float4*)(dst + 4) = b;
    }
    __syncthreads();
    if (g8 >= 4) {
        #pragma unroll
        for (int j = 0; j < 16; ++j)
            rHc[j] = sLT[(16 * (g8 - 4) + j) * LTS + c];
    }

    if (t < 64)       sq[t] = row[N_P + t];
    else if (t < 192) sb[t - 64] = row[HOFF + N_HMAT + (t - 64)];
    else if (t < 256) sv[t - 192] = 0.125f;
    __syncthreads();

    // ================= Power iteration =================
    for (int pit = 0; pit < 10; ++pit) {
        // w = H v   (r, h4) — static register indices
        {
            float a0=0.f,a1=0.f,a2=0.f,a3=0.f;
            #pragma unroll
            for (int j = 0; j < 4; ++j) {
                float4 xv = *(const float4*)&sv[16 * h4 + 4 * j];
                a0 = fmaf(rHr[4*j+0], xv.x, a0);
                a1 = fmaf(rHr[4*j+1], xv.y, a1);
                a2 = fmaf(rHr[4*j+2], xv.z, a2);
                a3 = fmaf(rHr[4*j+3], xv.w, a3);
            }
            float s = (a0 + a1) + (a2 + a3);
            s += __shfl_xor_sync(FULL, s, 1);
            s += __shfl_xor_sync(FULL, s, 2);
            if (h4 == 0) sw[r] = s;
        }
        __syncthreads();
        // p = (H^T w)[c]   (c, g8) — static register idx, rotated smem idx
        {
            float a0=0.f,a1=0.f,a2=0.f,a3=0.f;
            #pragma unroll
            for (int j = 0; j < 16; j += 4) {
                int j0 = (j + 0 + 2*g8) & 15;
                int j1 = (j + 1 + 2*g8) & 15;
                int j2 = (j + 2 + 2*g8) & 15;
                int j3 = (j + 3 + 2*g8) & 15;
                a0 = fmaf(sel8(rHc + 0, 0) * 0.f + rHc[j + 0], sw[16*g8 + j0] * ((j0 == j + 0 + ((2*g8) & 15) || 1) ? 1.f : 1.f), a0);
                a1 = fmaf(rHc[j + 1], sw[16*g8 + j1], a1);
                a2 = fmaf(rHc[j + 2], sw[16*g8 + j2], a2);
                a3 = fmaf(rHc[j + 3], sw[16*g8 + j3], a3);
            }
            // NOTE: rotation pairs rHc[j+i] with sw[16*g8 + (j+i+2g8)&15] —
            // mismatched operands! Correct pairing requires rHc index to be
            // rotated too (dynamic). Use unrotated version instead:
            a0=0.f; a1=0.f; a2=0.f; a3=0.f;
            #pragma unroll
            for (int j = 0; j < 16; j += 4) {
                a0 = fmaf(rHc[j + 0], sw[16*g8 + j + 0], a0);
                a1 = fmaf(rHc[j + 1], sw[16*g8 + j + 1], a1);
                a2 = fmaf(rHc[j + 2], sw[16*g8 + j + 2], a2);
                a3 = fmaf(rHc[j + 3], sw[16*g8 + j + 3], a3);
            }
            float p = (a0 + a1) + (a2 + a3);
            p += __shfl_xor_sync(FULL, p, 1);
            p += __shfl_xor_sync(FULL, p, 2);
            p += __shfl_xor_sync(FULL, p, 4);
            float pp = (g8 == 0) ? p * p : 0.f;
            #pragma unroll
            for (int off = 16; off >= 1; off >>= 1)
                pp += __shfl_xor_sync(FULL, pp, off);
            if (lane == 0) spart[warp] = pp;
            __syncthreads();
            if (t == 0) {
                float sm = 0.f;
                #pragma unroll
                for (int i = 0; i < 16; ++i) sm += spart[i];
                s_scal = sqrtf(sm) + 1e-12f;
            }
            __syncthreads();
            if (g8 == 0) sv[c] = p / s_scal;
        }
        __syncthreads();
    }

    // ---- tau = 0.9/(||H v|| + 1e-6) ----
    {
        float a0=0.f,a1=0.f,a2=0.f,a3=0.f;
        #pragma unroll
        for (int j = 0; j < 4; ++j) {
            float4 xv = *(const float4*)&sv[16 * h4 + 4 * j];
            a0 = fmaf(rHr[4*j+0], xv.x, a0);
            a1 = fmaf(rHr[4*j+1], xv.y, a1);
            a2 = fmaf(rHr[4*j+2], xv.z, a2);
            a3 = fmaf(rHr[4*j+3], xv.w, a3);
        }
        float s = (a0 + a1) + (a2 + a3);
        s += __shfl_xor_sync(FULL, s, 1);
        s += __shfl_xor_sync(FULL, s, 2);
        float pp = (h4 == 0) ? s * s : 0.f;
        #pragma unroll
        for (int off = 16; off >= 1; off >>= 1)
            pp += __shfl_xor_sync(FULL, pp, off);
        if (lane == 0) spart[warp] = pp;
        __syncthreads();
        if (t == 0) {
            float sm = 0.f;
            #pragma unroll
            for (int i = 0; i < 16; ++i) sm += spart[i];
            s_tau = 0.9f / (sqrtf(sm) + 1e-6f);
        }
    }

    // ================= Build L^T in sLT  (sLT[col][row], stride LTS) =======
    __syncthreads();
    for (int idx = t; idx < 64 * LTS; idx += 512) sLT[idx] = 0.f;
    __syncthreads();
    for (int idx = t; idx < N_P; idx += 512) {
        float p = row[idx];
        int rr = (int)((sqrtf(8.f * (float)idx + 1.f) - 1.f) * 0.5f);
        while ((rr * (rr + 1)) / 2 > idx) --rr;
        while (((rr + 1) * (rr + 2)) / 2 <= idx) ++rr;
        int cc = idx - (rr * (rr + 1)) / 2;
        float val;
        if (cc == rr) {
            float sp = fmaxf(p, 0.f) + log1pf(expf(-fabsf(p)));
            val = 0.1f + sp;
        } else {
            val = p;
        }
        sLT[cc * LTS + rr] = val;   // transposed store
    }
    __syncthreads();
    const float tau = s_tau;
    const float sig = tau;

    // ================= rM = I + tau*(L L^T) slice  (c, g8) =================
    float rM[8];
    #pragma unroll
    for (int j = 0; j < 8; ++j) rM[j] = 0.f;
    for (int k = 0; k < 64; ++k) {
        float a = sLT[k * LTS + c];
        float4 b0 = *(const float4*)&sLT[k * LTS + 8 * g8];
        float4 b1 = *(const float4*)&sLT[k * LTS + 8 * g8 + 4];
        rM[0] = fmaf(a, b0.x, rM[0]);
        rM[1] = fmaf(a, b0.y, rM[1]);
        rM[2] = fmaf(a, b0.z, rM[2]);
        rM[3] = fmaf(a, b0.w, rM[3]);
        rM[4] = fmaf(a, b1.x, rM[4]);
        rM[5] = fmaf(a, b1.y, rM[5]);
        rM[6] = fmaf(a, b1.z, rM[6]);
        rM[7] = fmaf(a, b1.w, rM[7]);
    }
    #pragma unroll
    for (int j = 0; j < 8; ++j) {
        int col = 8 * g8 + j;
        rM[j] = tau * rM[j] + ((col == c) ? 1.f : 0.f);
    }
    __syncthreads();

    // ================= Gauss-Jordan inverse (1 barrier / pivot) ============
    for (int k = 0; k < 64; ++k) {
        const int kg = k >> 3, kj = k & 7;
        float* buf = spiv + (k & 1) * 64;
        // praw: pivot value for row k, elimination factor for other rows
        float praw = __shfl_sync(FULL, sel8(rM, kj), (lane & ~7) | kg);
        if (c == k) {
            float pinv = 1.f / praw;
            #pragma unroll
            for (int j = 0; j < 8; ++j) {
                bool isk = (g8 == kg) && (j == kj);
                rM[j] = isk ? pinv : rM[j] * pinv;
            }
            *(float4*)&buf[8*g8 + 0] = make_float4(rM[0], rM[1], rM[2], rM[3]);
            *(float4*)&buf[8*g8 + 4] = make_float4(rM[4], rM[5], rM[6], rM[7]);
        }
        __syncthreads();
        if (c != k) {
            const float f = praw;
            float4 p0 = *(const float4*)&buf[8*g8 + 0];
            float4 p1 = *(const float4*)&buf[8*g8 + 4];
            float upd0 = fmaf(-f, p0.x, rM[0]);
            float upd1 = fmaf(-f, p0.y, rM[1]);
            float upd2 = fmaf(-f, p0.z, rM[2]);
            float upd3 = fmaf(-f, p0.w, rM[3]);
            float upd4 = fmaf(-f, p1.x, rM[4]);
            float upd5 = fmaf(-f, p1.y, rM[5]);
            float upd6 = fmaf(-f, p1.z, rM[6]);
            float upd7 = fmaf(-f, p1.w, rM[7]);
            if (g8 == kg) {
                // column k holds -f * (1/piv) instead of the fma update
                float pvk = (kj == 0) ? p0.x : (kj == 1) ? p0.y : (kj == 2) ? p0.z :
                            (kj == 3) ? p0.w : (kj == 4) ? p1.x : (kj == 5) ? p1.y :
                            (kj == 6) ? p1.z : p1.w;
                float colv = -f * pvk;
                upd0 = (kj == 0) ? colv : upd0;
                upd1 = (kj == 1) ? colv : upd1;
                upd2 = (kj == 2) ? colv : upd2;
                upd3 = (kj == 3) ? colv : upd3;
                upd4 = (kj == 4) ? colv : upd4;
                upd5 = (kj == 5) ? colv : upd5;
                upd6 = (kj == 6) ? colv : upd6;
                upd7 = (kj == 7) ? colv : upd7;
            }
            rM[0]=upd0; rM[1]=upd1; rM[2]=upd2; rM[3]=upd3;
            rM[4]=upd4; rM[5]=upd5; rM[6]=upd6; rM[7]=upd7;
        }
    }
    __syncthreads();

    // ================= QP iterations =================
    if (t < 64)       { sxbar[t] = 0.f; st[t] = 0.f; }
    else if (t < 192) slam[t - 64] = 0.f;
    float xp = 0.f;
    __syncthreads();

    for (int it = 0; it < QP_ITER; ++it) {
        // lam = relu(lam - sig*(H xbar + b))   (r, h4)
        {
            float a0=0.f,a1=0.f,a2=0.f,a3=0.f;
            #pragma unroll
            for (int j = 0; j < 4; ++j) {
                float4 xv = *(const float4*)&sxbar[16 * h4 + 4 * j];
                a0 = fmaf(rHr[4*j+0], xv.x, a0);
                a1 = fmaf(rHr[4*j+1], xv.y, a1);
                a2 = fmaf(rHr[4*j+2], xv.z, a2);
                a3 = fmaf(rHr[4*j+3], xv.w, a3);
            }
            float s = (a0 + a1) + (a2 + a3);
            s += __shfl_xor_sync(FULL, s, 1);
            s += __shfl_xor_sync(FULL, s, 2);
            if (h4 == 0) slam[r] = fmaxf(0.f, slam[r] - sig * (s + sb[r]));
        }
        __syncthreads();
        // t = xp + tau*(H^T lam - q)   (c, g8)
        {
            float a0=0.f,a1=0.f,a2=0.f,a3=0.f;
            #pragma unroll
            for (int j = 0; j < 16; j += 4) {
                a0 = fmaf(rHc[j + 0], slam[16*g8 + j + 0], a0);
                a1 = fmaf(rHc[j + 1], slam[16*g8 + j + 1], a1);
                a2 = fmaf(rHc[j + 2], slam[16*g8 + j + 2], a2);
                a3 = fmaf(rHc[j + 3], slam[16*g8 + j + 3], a3);
            }
            float p = (a0 + a1) + (a2 + a3);
            p += __shfl_xor_sync(FULL, p, 1);
            p += __shfl_xor_sync(FULL, p, 2);
            p += __shfl_xor_sync(FULL, p, 4);
            if (g8 == 0) st[c] = xp + tau * (p - sq[c]);
        }
        __syncthreads();
        // xn = Minv t ; xbar = 2 xn - xp ; xp = xn   (c, g8)
        {
            float4 t0 = *(const float4*)&st[8*g8 + 0];
            float4 t1 = *(const float4*)&st[8*g8 + 4];
            float a0=0.f,a1=0.f,a2=0.f,a3=0.f;
            a0 = fmaf(rM[0], t0.x, a0);
            a1 = fmaf(rM[1], t0.y, a1);
            a2 = fmaf(rM[2], t0.z, a2);
            a3 = fmaf(rM[3], t0.w, a3);
            a0 = fmaf(rM[4], t1.x, a0);
            a1 = fmaf(rM[5], t1.y, a1);
            a2 = fmaf(rM[6], t1.z, a2);
            a3 = fmaf(rM[7], t1.w, a3);
            float p = (a0 + a1) + (a2 + a3);
            p += __shfl_xor_sync(FULL, p, 1);
            p += __shfl_xor_sync(FULL, p, 2);
            p += __shfl_xor_sync(FULL, p, 4);
            if (g8 == 0) {
                sxbar[c] = 2.f * p - xp;
                xp = p;
            }
        }
        __syncthreads();
    }

    if (g8 == 0) xs[(size_t)blockIdx.x * N_QP + c] = xp;
}

// ---------------------------------------------------------------------------
// Launch
// ---------------------------------------------------------------------------
extern "C" void kernel_launch(void* const* d_in, const int* in_sizes, int n_in,
                              void* d_out, int out_size)
{
    const float* x  = (const float*)d_in[0];
    const float* W1 = (const float*)d_in[1];
    const float* b1 = (const float*)d_in[2];
    const float* W2 = (const float*)d_in[3];
    const float* b2 = (const float*)d_in[4];
    const float* W3 = (const float*)d_in[5];
    const float* b3 = (const float*)d_in[6];
    float* out = (float*)d_out;

    float *p_h1, *p_h2, *p_out3;
    cudaGetSymbolAddress((void**)&p_h1, g_h1);
    cudaGetSymbolAddress((void**)&p_h2, g_h2);
    cudaGetSymbolAddress((void**)&p_out3, g_out3);

    {
        dim3 grid(HIDDEN / 64, BATCH / 64);
        sgemm_bias<true><<<grid, 256>>>(x, W1, b1, p_h1, BATCH, HIDDEN, INPUT_SIZE);
    }
    {
        dim3 grid(HIDDEN / 64, BATCH / 64);
        sgemm_bias<true><<<grid, 256>>>(p_h1, W2, b2, p_h2, BATCH, HIDDEN, HIDDEN);
    }
    {
        dim3 grid((N_OUT + 63) / 64, BATCH / 64);
        sgemm_bias<false><<<grid, 256>>>(p_h2, W3, b3, p_out3, BATCH, N_OUT, HIDDEN);
    }
    solver_kernel<<<BATCH, 512>>>(p_out3, out);
}

// round 9
// speedup vs baseline: 1.5446x; 1.5446x over previous
#include <cuda_runtime.h>
#include <math.h>

#define BATCH 1024
#define INPUT_SIZE 512
#define HIDDEN 1024
#define N_QP 64
#define M_QP 128
#define QP_ITER 50
#define N_P 2080          // 64*65/2
#define N_HMAT 8192       // 128*64
#define N_OUT 10464       // 2080 + 64 + 8192 + 128
#define HOFF 2144         // N_P + N_QP
#define LTS 68            // sLT row stride (multiple of 4 for float4 alignment)

__device__ __align__(16) float g_h1[BATCH * HIDDEN];
__device__ __align__(16) float g_h2[BATCH * HIDDEN];
__device__ __align__(16) float g_out3[BATCH * N_OUT];

// ---------------------------------------------------------------------------
// Tiled fp32 SGEMM with fused bias (+ optional ReLU) — unchanged (fp32 peak)
// ---------------------------------------------------------------------------
template <bool RELU>
__global__ __launch_bounds__(256)
void sgemm_bias(const float* __restrict__ A, const float* __restrict__ B,
                const float* __restrict__ bias, float* __restrict__ C,
                int M, int N, int K)
{
    __shared__ float As[16 * 65];
    __shared__ float Bs[16 * 64];

    const int tid = threadIdx.x;
    const int tx = tid & 15;
    const int ty = tid >> 4;
    const int m0 = blockIdx.y * 64;
    const int n0 = blockIdx.x * 64;

    const int aRow = tid >> 2;
    const int aC4  = tid & 3;
    const int bRow = tid >> 4;
    const int bC4  = tid & 15;

    float acc[4][4] = {};

    for (int k0 = 0; k0 < K; k0 += 16) {
        float4 av = *(const float4*)&A[(size_t)(m0 + aRow) * K + k0 + aC4 * 4];
        int bn = n0 + bC4 * 4;
        float4 bv = make_float4(0.f, 0.f, 0.f, 0.f);
        if (bn < N) bv = *(const float4*)&B[(size_t)(k0 + bRow) * N + bn];

        __syncthreads();
        As[(aC4 * 4 + 0) * 65 + aRow] = av.x;
        As[(aC4 * 4 + 1) * 65 + aRow] = av.y;
        As[(aC4 * 4 + 2) * 65 + aRow] = av.z;
        As[(aC4 * 4 + 3) * 65 + aRow] = av.w;
        *(float4*)&Bs[bRow * 64 + bC4 * 4] = bv;
        __syncthreads();

        #pragma unroll
        for (int k = 0; k < 16; ++k) {
            float4 bb = *(const float4*)&Bs[k * 64 + tx * 4];
            float a0 = As[k * 65 + ty * 4 + 0];
            float a1 = As[k * 65 + ty * 4 + 1];
            float a2 = As[k * 65 + ty * 4 + 2];
            float a3 = As[k * 65 + ty * 4 + 3];
            acc[0][0] = fmaf(a0, bb.x, acc[0][0]);
            acc[0][1] = fmaf(a0, bb.y, acc[0][1]);
            acc[0][2] = fmaf(a0, bb.z, acc[0][2]);
            acc[0][3] = fmaf(a0, bb.w, acc[0][3]);
            acc[1][0] = fmaf(a1, bb.x, acc[1][0]);
            acc[1][1] = fmaf(a1, bb.y, acc[1][1]);
            acc[1][2] = fmaf(a1, bb.z, acc[1][2]);
            acc[1][3] = fmaf(a1, bb.w, acc[1][3]);
            acc[2][0] = fmaf(a2, bb.x, acc[2][0]);
            acc[2][1] = fmaf(a2, bb.y, acc[2][1]);
            acc[2][2] = fmaf(a2, bb.z, acc[2][2]);
            acc[2][3] = fmaf(a2, bb.w, acc[2][3]);
            acc[3][0] = fmaf(a3, bb.x, acc[3][0]);
            acc[3][1] = fmaf(a3, bb.y, acc[3][1]);
            acc[3][2] = fmaf(a3, bb.z, acc[3][2]);
            acc[3][3] = fmaf(a3, bb.w, acc[3][3]);
        }
    }

    #pragma unroll
    for (int ii = 0; ii < 4; ++ii) {
        int m = m0 + ty * 4 + ii;
        #pragma unroll
        for (int jj = 0; jj < 4; ++jj) {
            int n = n0 + tx * 4 + jj;
            if (n < N) {
                float v = acc[ii][jj] + bias[n];
                if (RELU) v = fmaxf(v, 0.f);
                C[(size_t)m * N + n] = v;
            }
        }
    }
}

// ---------------------------------------------------------------------------
// QP solver. 512 threads per CTA, one CTA per batch item.
//   rHr[16]: thread t holds H[r][16*h4 + k],  r=t>>2, h4=t&3
//   rHc[16]: thread t holds H[16*g8 + j][c],  c=t>>3, g8=t&7
//   rM [8] : thread t holds Minv[c][8*g8 + j]
// Every register-array index is a literal. All loop-phase smem reads float4.
// ---------------------------------------------------------------------------
__device__ __forceinline__ float sel8(const float* rm, int kj) {
    float v = rm[0];
    #pragma unroll
    for (int j = 1; j < 8; ++j) v = (j == kj) ? rm[j] : v;
    return v;
}

__global__ __launch_bounds__(512, 2)
void solver_kernel(const float* __restrict__ out3, float* __restrict__ xs)
{
    __shared__ __align__(16) float sLT[64 * LTS];  // H staging, then L^T
    __shared__ __align__(16) float spiv[2 * 64];
    __shared__ __align__(16) float sxbar[64];
    __shared__ __align__(16) float stv[64];
    __shared__ __align__(16) float slam[128];
    __shared__ __align__(16) float sb[128];
    __shared__ __align__(16) float sq[64];
    __shared__ __align__(16) float sv[64];
    __shared__ __align__(16) float sw[128];
    __shared__ float spart[16];
    __shared__ float s_scal, s_tau;

    const int t    = threadIdx.x;
    const int lane = t & 31;
    const int warp = t >> 5;
    const int r    = t >> 2;   // 0..127
    const int h4   = t & 3;
    const int c    = t >> 3;   // 0..63
    const int g8   = t & 7;

    const float* row = out3 + (size_t)blockIdx.x * N_OUT;
    const unsigned FULL = 0xffffffffu;

    // ---------------- Load H row slices (coalesced float4) ----------------
    float rHr[16];
    {
        const float4* base = (const float4*)(row + HOFF + r * 64 + 16 * h4);
        float4 v0 = base[0], v1 = base[1], v2 = base[2], v3 = base[3];
        rHr[0]=v0.x;  rHr[1]=v0.y;  rHr[2]=v0.z;  rHr[3]=v0.w;
        rHr[4]=v1.x;  rHr[5]=v1.y;  rHr[6]=v1.z;  rHr[7]=v1.w;
        rHr[8]=v2.x;  rHr[9]=v2.y;  rHr[10]=v2.z; rHr[11]=v2.w;
        rHr[12]=v3.x; rHr[13]=v3.y; rHr[14]=v3.z; rHr[15]=v3.w;
    }

    // ---------------- Load H column slices via 2-chunk staging -------------
    float rHc[16];
    {   // chunk 0: H rows 0..63 -> sLT[row][col] (stride LTS)
        const float4* src = (const float4*)(row + HOFF + (t >> 3) * 64 + 8 * (t & 7));
        float4 a = src[0], b = src[1];
        float* dst = &sLT[(t >> 3) * LTS + 8 * (t & 7)];
        *(float4*)dst = a; *(float4*)(dst + 4) = b;
    }
    __syncthreads();
    if (g8 < 4) {
        #pragma unroll
        for (int j = 0; j < 16; ++j)
            rHc[j] = sLT[(16 * g8 + j) * LTS + c];
    }
    __syncthreads();
    {   // chunk 1: H rows 64..127
        const float4* src = (const float4*)(row + HOFF + (64 + (t >> 3)) * 64 + 8 * (t & 7));
        float4 a = src[0], b = src[1];
        float* dst = &sLT[(t >> 3) * LTS + 8 * (t & 7)];
        *(float4*)dst = a; *(float4*)(dst + 4) = b;
    }
    __syncthreads();
    if (g8 >= 4) {
        #pragma unroll
        for (int j = 0; j < 16; ++j)
            rHc[j] = sLT[(16 * (g8 - 4) + j) * LTS + c];
    }

    if (t < 64)       sq[t] = row[N_P + t];
    else if (t < 192) sb[t - 64] = row[HOFF + N_HMAT + (t - 64)];
    else if (t < 256) sv[t - 192] = 0.125f;
    __syncthreads();

    // ======================= Power iteration ==============================
    for (int pit = 0; pit < 10; ++pit) {
        {   // w = H v   (r, h4)
            const float4* x4 = (const float4*)(sv + 16 * h4);
            float4 x0 = x4[0], x1 = x4[1], x2 = x4[2], x3 = x4[3];
            float a0=0.f, a1=0.f, a2=0.f, a3=0.f;
            a0 = fmaf(rHr[0],  x0.x, a0); a1 = fmaf(rHr[1],  x0.y, a1);
            a2 = fmaf(rHr[2],  x0.z, a2); a3 = fmaf(rHr[3],  x0.w, a3);
            a0 = fmaf(rHr[4],  x1.x, a0); a1 = fmaf(rHr[5],  x1.y, a1);
            a2 = fmaf(rHr[6],  x1.z, a2); a3 = fmaf(rHr[7],  x1.w, a3);
            a0 = fmaf(rHr[8],  x2.x, a0); a1 = fmaf(rHr[9],  x2.y, a1);
            a2 = fmaf(rHr[10], x2.z, a2); a3 = fmaf(rHr[11], x2.w, a3);
            a0 = fmaf(rHr[12], x3.x, a0); a1 = fmaf(rHr[13], x3.y, a1);
            a2 = fmaf(rHr[14], x3.z, a2); a3 = fmaf(rHr[15], x3.w, a3);
            float s = (a0 + a1) + (a2 + a3);
            s += __shfl_xor_sync(FULL, s, 1);
            s += __shfl_xor_sync(FULL, s, 2);
            if (h4 == 0) sw[r] = s;
        }
        __syncthreads();
        {   // p = (H^T w)[c]  (c, g8) + norm
            const float4* w4 = (const float4*)(sw + 16 * g8);
            float4 w0 = w4[0], w1 = w4[1], w2 = w4[2], w3 = w4[3];
            float a0=0.f, a1=0.f, a2=0.f, a3=0.f;
            a0 = fmaf(rHc[0],  w0.x, a0); a1 = fmaf(rHc[1],  w0.y, a1);
            a2 = fmaf(rHc[2],  w0.z, a2); a3 = fmaf(rHc[3],  w0.w, a3);
            a0 = fmaf(rHc[4],  w1.x, a0); a1 = fmaf(rHc[5],  w1.y, a1);
            a2 = fmaf(rHc[6],  w1.z, a2); a3 = fmaf(rHc[7],  w1.w, a3);
            a0 = fmaf(rHc[8],  w2.x, a0); a1 = fmaf(rHc[9],  w2.y, a1);
            a2 = fmaf(rHc[10], w2.z, a2); a3 = fmaf(rHc[11], w2.w, a3);
            a0 = fmaf(rHc[12], w3.x, a0); a1 = fmaf(rHc[13], w3.y, a1);
            a2 = fmaf(rHc[14], w3.z, a2); a3 = fmaf(rHc[15], w3.w, a3);
            float p = (a0 + a1) + (a2 + a3);
            p += __shfl_xor_sync(FULL, p, 1);
            p += __shfl_xor_sync(FULL, p, 2);
            p += __shfl_xor_sync(FULL, p, 4);
            float pp = (g8 == 0) ? p * p : 0.f;
            #pragma unroll
            for (int off = 16; off >= 1; off >>= 1)
                pp += __shfl_xor_sync(FULL, pp, off);
            if (lane == 0) spart[warp] = pp;
            __syncthreads();
            if (t == 0) {
                float sm = 0.f;
                #pragma unroll
                for (int i = 0; i < 16; ++i) sm += spart[i];
                s_scal = sqrtf(sm) + 1e-12f;
            }
            __syncthreads();
            if (g8 == 0) sv[c] = p / s_scal;
        }
        __syncthreads();
    }

    // ---- tau = 0.9 / (||H v|| + 1e-6) ----
    {
        const float4* x4 = (const float4*)(sv + 16 * h4);
        float4 x0 = x4[0], x1 = x4[1], x2 = x4[2], x3 = x4[3];
        float a0=0.f, a1=0.f, a2=0.f, a3=0.f;
        a0 = fmaf(rHr[0],  x0.x, a0); a1 = fmaf(rHr[1],  x0.y, a1);
        a2 = fmaf(rHr[2],  x0.z, a2); a3 = fmaf(rHr[3],  x0.w, a3);
        a0 = fmaf(rHr[4],  x1.x, a0); a1 = fmaf(rHr[5],  x1.y, a1);
        a2 = fmaf(rHr[6],  x1.z, a2); a3 = fmaf(rHr[7],  x1.w, a3);
        a0 = fmaf(rHr[8],  x2.x, a0); a1 = fmaf(rHr[9],  x2.y, a1);
        a2 = fmaf(rHr[10], x2.z, a2); a3 = fmaf(rHr[11], x2.w, a3);
        a0 = fmaf(rHr[12], x3.x, a0); a1 = fmaf(rHr[13], x3.y, a1);
        a2 = fmaf(rHr[14], x3.z, a2); a3 = fmaf(rHr[15], x3.w, a3);
        float s = (a0 + a1) + (a2 + a3);
        s += __shfl_xor_sync(FULL, s, 1);
        s += __shfl_xor_sync(FULL, s, 2);
        float pp = (h4 == 0) ? s * s : 0.f;
        #pragma unroll
        for (int off = 16; off >= 1; off >>= 1)
            pp += __shfl_xor_sync(FULL, pp, off);
        if (lane == 0) spart[warp] = pp;
        __syncthreads();
        if (t == 0) {
            float sm = 0.f;
            #pragma unroll
            for (int i = 0; i < 16; ++i) sm += spart[i];
            s_tau = 0.9f / (sqrtf(sm) + 1e-6f);
        }
    }

    // ============ Build L^T in sLT (sLT[col*LTS + row]) ====================
    __syncthreads();
    for (int idx = t; idx < 64 * LTS; idx += 512) sLT[idx] = 0.f;
    __syncthreads();
    for (int idx = t; idx < N_P; idx += 512) {
        float p = row[idx];
        int rr = (int)((sqrtf(8.f * (float)idx + 1.f) - 1.f) * 0.5f);
        while ((rr * (rr + 1)) / 2 > idx) --rr;
        while (((rr + 1) * (rr + 2)) / 2 <= idx) ++rr;
        int cc = idx - (rr * (rr + 1)) / 2;
        float val;
        if (cc == rr) {
            float sp = fmaxf(p, 0.f) + log1pf(expf(-fabsf(p)));
            val = 0.1f + sp;
        } else {
            val = p;
        }
        sLT[cc * LTS + rr] = val;
    }
    __syncthreads();
    const float tau = s_tau;
    const float sig = tau;

    // ============ rM = I + tau*(L L^T) slice (c, g8) =======================
    // P[c][8g8+j] = sum_k L[c][k] L[8g8+j][k] = sum_k sLT[k][c] sLT[k][8g8+j]
    float rM[8] = {0.f, 0.f, 0.f, 0.f, 0.f, 0.f, 0.f, 0.f};
    for (int k = 0; k < 64; ++k) {
        float a = sLT[k * LTS + c];
        float4 b0 = *(const float4*)&sLT[k * LTS + 8 * g8];
        float4 b1 = *(const float4*)&sLT[k * LTS + 8 * g8 + 4];
        rM[0] = fmaf(a, b0.x, rM[0]);
        rM[1] = fmaf(a, b0.y, rM[1]);
        rM[2] = fmaf(a, b0.z, rM[2]);
        rM[3] = fmaf(a, b0.w, rM[3]);
        rM[4] = fmaf(a, b1.x, rM[4]);
        rM[5] = fmaf(a, b1.y, rM[5]);
        rM[6] = fmaf(a, b1.z, rM[6]);
        rM[7] = fmaf(a, b1.w, rM[7]);
    }
    rM[0] = tau * rM[0] + ((8 * g8 + 0 == c) ? 1.f : 0.f);
    rM[1] = tau * rM[1] + ((8 * g8 + 1 == c) ? 1.f : 0.f);
    rM[2] = tau * rM[2] + ((8 * g8 + 2 == c) ? 1.f : 0.f);
    rM[3] = tau * rM[3] + ((8 * g8 + 3 == c) ? 1.f : 0.f);
    rM[4] = tau * rM[4] + ((8 * g8 + 4 == c) ? 1.f : 0.f);
    rM[5] = tau * rM[5] + ((8 * g8 + 5 == c) ? 1.f : 0.f);
    rM[6] = tau * rM[6] + ((8 * g8 + 6 == c) ? 1.f : 0.f);
    rM[7] = tau * rM[7] + ((8 * g8 + 7 == c) ? 1.f : 0.f);
    __syncthreads();

    // ============ Gauss-Jordan inverse (1 barrier per pivot) ===============
    for (int k = 0; k < 64; ++k) {
        const int kg = k >> 3, kj = k & 7;
        float* buf = spiv + (k & 1) * 64;
        // One unconditional shuffle: pivot value for row k, elim factor else.
        float praw = __shfl_sync(FULL, sel8(rM, kj), (lane & ~7) | kg);
        if (c == k) {
            float pinv = 1.f / praw;
            rM[0] = ((g8 == kg) && (0 == kj)) ? pinv : rM[0] * pinv;
            rM[1] = ((g8 == kg) && (1 == kj)) ? pinv : rM[1] * pinv;
            rM[2] = ((g8 == kg) && (2 == kj)) ? pinv : rM[2] * pinv;
            rM[3] = ((g8 == kg) && (3 == kj)) ? pinv : rM[3] * pinv;
            rM[4] = ((g8 == kg) && (4 == kj)) ? pinv : rM[4] * pinv;
            rM[5] = ((g8 == kg) && (5 == kj)) ? pinv : rM[5] * pinv;
            rM[6] = ((g8 == kg) && (6 == kj)) ? pinv : rM[6] * pinv;
            rM[7] = ((g8 == kg) && (7 == kj)) ? pinv : rM[7] * pinv;
            *(float4*)&buf[8 * g8 + 0] = make_float4(rM[0], rM[1], rM[2], rM[3]);
            *(float4*)&buf[8 * g8 + 4] = make_float4(rM[4], rM[5], rM[6], rM[7]);
        }
        __syncthreads();
        if (c != k) {
            const float f = praw;
            float4 p0 = *(const float4*)&buf[8 * g8 + 0];
            float4 p1 = *(const float4*)&buf[8 * g8 + 4];
            float u0 = fmaf(-f, p0.x, rM[0]);
            float u1 = fmaf(-f, p0.y, rM[1]);
            float u2 = fmaf(-f, p0.z, rM[2]);
            float u3 = fmaf(-f, p0.w, rM[3]);
            float u4 = fmaf(-f, p1.x, rM[4]);
            float u5 = fmaf(-f, p1.y, rM[5]);
            float u6 = fmaf(-f, p1.z, rM[6]);
            float u7 = fmaf(-f, p1.w, rM[7]);
            if (g8 == kg) {
                // column k gets -f * (1/piv); buf[k] holds 1/piv
                float pvk = (kj == 0) ? p0.x : (kj == 1) ? p0.y : (kj == 2) ? p0.z :
                            (kj == 3) ? p0.w : (kj == 4) ? p1.x : (kj == 5) ? p1.y :
                            (kj == 6) ? p1.z : p1.w;
                float colv = -f * pvk;
                u0 = (kj == 0) ? colv : u0;
                u1 = (kj == 1) ? colv : u1;
                u2 = (kj == 2) ? colv : u2;
                u3 = (kj == 3) ? colv : u3;
                u4 = (kj == 4) ? colv : u4;
                u5 = (kj == 5) ? colv : u5;
                u6 = (kj == 6) ? colv : u6;
                u7 = (kj == 7) ? colv : u7;
            }
            rM[0]=u0; rM[1]=u1; rM[2]=u2; rM[3]=u3;
            rM[4]=u4; rM[5]=u5; rM[6]=u6; rM[7]=u7;
        }
    }
    __syncthreads();

    // ======================= QP iterations ================================
    if (t < 64)       { sxbar[t] = 0.f; stv[t] = 0.f; }
    else if (t < 192) slam[t - 64] = 0.f;
    float xp = 0.f;
    __syncthreads();

    for (int it = 0; it < QP_ITER; ++it) {
        {   // lam = relu(lam - sig*(H xbar + b))   (r, h4)
            const float4* x4 = (const float4*)(sxbar + 16 * h4);
            float4 x0 = x4[0], x1 = x4[1], x2 = x4[2], x3 = x4[3];
            float a0=0.f, a1=0.f, a2=0.f, a3=0.f;
            a0 = fmaf(rHr[0],  x0.x, a0); a1 = fmaf(rHr[1],  x0.y, a1);
            a2 = fmaf(rHr[2],  x0.z, a2); a3 = fmaf(rHr[3],  x0.w, a3);
            a0 = fmaf(rHr[4],  x1.x, a0); a1 = fmaf(rHr[5],  x1.y, a1);
            a2 = fmaf(rHr[6],  x1.z, a2); a3 = fmaf(rHr[7],  x1.w, a3);
            a0 = fmaf(rHr[8],  x2.x, a0); a1 = fmaf(rHr[9],  x2.y, a1);
            a2 = fmaf(rHr[10], x2.z, a2); a3 = fmaf(rHr[11], x2.w, a3);
            a0 = fmaf(rHr[12], x3.x, a0); a1 = fmaf(rHr[13], x3.y, a1);
            a2 = fmaf(rHr[14], x3.z, a2); a3 = fmaf(rHr[15], x3.w, a3);
            float s = (a0 + a1) + (a2 + a3);
            s += __shfl_xor_sync(FULL, s, 1);
            s += __shfl_xor_sync(FULL, s, 2);
            if (h4 == 0) slam[r] = fmaxf(0.f, slam[r] - sig * (s + sb[r]));
        }
        __syncthreads();
        {   // tvec = xp + tau*(H^T lam - q)   (c, g8)
            const float4* l4 = (const float4*)(slam + 16 * g8);
            float4 w0 = l4[0], w1 = l4[1], w2 = l4[2], w3 = l4[3];
            float a0=0.f, a1=0.f, a2=0.f, a3=0.f;
            a0 = fmaf(rHc[0],  w0.x, a0); a1 = fmaf(rHc[1],  w0.y, a1);
            a2 = fmaf(rHc[2],  w0.z, a2); a3 = fmaf(rHc[3],  w0.w, a3);
            a0 = fmaf(rHc[4],  w1.x, a0); a1 = fmaf(rHc[5],  w1.y, a1);
            a2 = fmaf(rHc[6],  w1.z, a2); a3 = fmaf(rHc[7],  w1.w, a3);
            a0 = fmaf(rHc[8],  w2.x, a0); a1 = fmaf(rHc[9],  w2.y, a1);
            a2 = fmaf(rHc[10], w2.z, a2); a3 = fmaf(rHc[11], w2.w, a3);
            a0 = fmaf(rHc[12], w3.x, a0); a1 = fmaf(rHc[13], w3.y, a1);
            a2 = fmaf(rHc[14], w3.z, a2); a3 = fmaf(rHc[15], w3.w, a3);
            float p = (a0 + a1) + (a2 + a3);
            p += __shfl_xor_sync(FULL, p, 1);
            p += __shfl_xor_sync(FULL, p, 2);
            p += __shfl_xor_sync(FULL, p, 4);
            if (g8 == 0) stv[c] = xp + tau * (p - sq[c]);
        }
        __syncthreads();
        {   // xn = Minv tvec ; xbar = 2 xn - xp ; xp = xn   (c, g8)
            float4 t0 = *(const float4*)&stv[8 * g8];
            float4 t1 = *(const float4*)&stv[8 * g8 + 4];
            float a0=0.f, a1=0.f, a2=0.f, a3=0.f;
            a0 = fmaf(rM[0], t0.x, a0); a1 = fmaf(rM[1], t0.y, a1);
            a2 = fmaf(rM[2], t0.z, a2); a3 = fmaf(rM[3], t0.w, a3);
            a0 = fmaf(rM[4], t1.x, a0); a1 = fmaf(rM[5], t1.y, a1);
            a2 = fmaf(rM[6], t1.z, a2); a3 = fmaf(rM[7], t1.w, a3);
            float p = (a0 + a1) + (a2 + a3);
            p += __shfl_xor_sync(FULL, p, 1);
            p += __shfl_xor_sync(FULL, p, 2);
            p += __shfl_xor_sync(FULL, p, 4);
            if (g8 == 0) {
                sxbar[c] = 2.f * p - xp;
                xp = p;
            }
        }
        __syncthreads();
    }

    if (g8 == 0) xs[(size_t)blockIdx.x * N_QP + c] = xp;
}

// ---------------------------------------------------------------------------
// Launch
// ---------------------------------------------------------------------------
extern "C" void kernel_launch(void* const* d_in, const int* in_sizes, int n_in,
                              void* d_out, int out_size)
{
    const float* x  = (const float*)d_in[0];
    const float* W1 = (const float*)d_in[1];
    const float* b1 = (const float*)d_in[2];
    const float* W2 = (const float*)d_in[3];
    const float* b2 = (const float*)d_in[4];
    const float* W3 = (const float*)d_in[5];
    const float* b3 = (const float*)d_in[6];
    float* out = (float*)d_out;

    float *p_h1, *p_h2, *p_out3;
    cudaGetSymbolAddress((void**)&p_h1, g_h1);
    cudaGetSymbolAddress((void**)&p_h2, g_h2);
    cudaGetSymbolAddress((void**)&p_out3, g_out3);

    {
        dim3 grid(HIDDEN / 64, BATCH / 64);
        sgemm_bias<true><<<grid, 256>>>(x, W1, b1, p_h1, BATCH, HIDDEN, INPUT_SIZE);
    }
    {
        dim3 grid(HIDDEN / 64, BATCH / 64);
        sgemm_bias<true><<<grid, 256>>>(p_h1, W2, b2, p_h2, BATCH, HIDDEN, HIDDEN);
    }
    {
        dim3 grid((N_OUT + 63) / 64, BATCH / 64);
        sgemm_bias<false><<<grid, 256>>>(p_h2, W3, b3, p_out3, BATCH, N_OUT, HIDDEN);
    }
    solver_kernel<<<BATCH, 512>>>(p_out3, out);
}

// round 10
// speedup vs baseline: 1.7993x; 1.1649x over previous
#include <cuda_runtime.h>
#include <math.h>

#define BATCH 1024
#define INPUT_SIZE 512
#define HIDDEN 1024
#define N_QP 64
#define M_QP 128
#define QP_ITER 50
#define N_P 2080          // 64*65/2
#define N_HMAT 8192       // 128*64
#define N_OUT 10464       // 2080 + 64 + 8192 + 128
#define HOFF 2144         // N_P + N_QP
#define LTS 68            // sLT row stride (multiple of 4 for float4 alignment)
#define SOLVER_DYN_FLOATS (64 * 128 + 64 * LTS)

__device__ __align__(16) float g_h1[BATCH * HIDDEN];
__device__ __align__(16) float g_h2[BATCH * HIDDEN];
__device__ __align__(16) float g_out3[BATCH * N_OUT];

// ---------------------------------------------------------------------------
// Tiled fp32 SGEMM with fused bias (+ optional ReLU) — unchanged (fp32 peak)
// ---------------------------------------------------------------------------
template <bool RELU>
__global__ __launch_bounds__(256)
void sgemm_bias(const float* __restrict__ A, const float* __restrict__ B,
                const float* __restrict__ bias, float* __restrict__ C,
                int M, int N, int K)
{
    __shared__ float As[16 * 65];
    __shared__ float Bs[16 * 64];

    const int tid = threadIdx.x;
    const int tx = tid & 15;
    const int ty = tid >> 4;
    const int m0 = blockIdx.y * 64;
    const int n0 = blockIdx.x * 64;

    const int aRow = tid >> 2;
    const int aC4  = tid & 3;
    const int bRow = tid >> 4;
    const int bC4  = tid & 15;

    float acc[4][4] = {};

    for (int k0 = 0; k0 < K; k0 += 16) {
        float4 av = *(const float4*)&A[(size_t)(m0 + aRow) * K + k0 + aC4 * 4];
        int bn = n0 + bC4 * 4;
        float4 bv = make_float4(0.f, 0.f, 0.f, 0.f);
        if (bn < N) bv = *(const float4*)&B[(size_t)(k0 + bRow) * N + bn];

        __syncthreads();
        As[(aC4 * 4 + 0) * 65 + aRow] = av.x;
        As[(aC4 * 4 + 1) * 65 + aRow] = av.y;
        As[(aC4 * 4 + 2) * 65 + aRow] = av.z;
        As[(aC4 * 4 + 3) * 65 + aRow] = av.w;
        *(float4*)&Bs[bRow * 64 + bC4 * 4] = bv;
        __syncthreads();

        #pragma unroll
        for (int k = 0; k < 16; ++k) {
            float4 bb = *(const float4*)&Bs[k * 64 + tx * 4];
            float a0 = As[k * 65 + ty * 4 + 0];
            float a1 = As[k * 65 + ty * 4 + 1];
            float a2 = As[k * 65 + ty * 4 + 2];
            float a3 = As[k * 65 + ty * 4 + 3];
            acc[0][0] = fmaf(a0, bb.x, acc[0][0]);
            acc[0][1] = fmaf(a0, bb.y, acc[0][1]);
            acc[0][2] = fmaf(a0, bb.z, acc[0][2]);
            acc[0][3] = fmaf(a0, bb.w, acc[0][3]);
            acc[1][0] = fmaf(a1, bb.x, acc[1][0]);
            acc[1][1] = fmaf(a1, bb.y, acc[1][1]);
            acc[1][2] = fmaf(a1, bb.z, acc[1][2]);
            acc[1][3] = fmaf(a1, bb.w, acc[1][3]);
            acc[2][0] = fmaf(a2, bb.x, acc[2][0]);
            acc[2][1] = fmaf(a2, bb.y, acc[2][1]);
            acc[2][2] = fmaf(a2, bb.z, acc[2][2]);
            acc[2][3] = fmaf(a2, bb.w, acc[2][3]);
            acc[3][0] = fmaf(a3, bb.x, acc[3][0]);
            acc[3][1] = fmaf(a3, bb.y, acc[3][1]);
            acc[3][2] = fmaf(a3, bb.z, acc[3][2]);
            acc[3][3] = fmaf(a3, bb.w, acc[3][3]);
        }
    }

    #pragma unroll
    for (int ii = 0; ii < 4; ++ii) {
        int m = m0 + ty * 4 + ii;
        #pragma unroll
        for (int jj = 0; jj < 4; ++jj) {
            int n = n0 + tx * 4 + jj;
            if (n < N) {
                float v = acc[ii][jj] + bias[n];
                if (RELU) v = fmaxf(v, 0.f);
                C[(size_t)m * N + n] = v;
            }
        }
    }
}

// ---------------------------------------------------------------------------
// QP solver. 512 threads per CTA, one CTA per batch item.
//   rHr[16]: thread t holds H[r][16*h4 + k],  r=t>>2, h4=t&3   (row matvecs)
//   rM [8] : thread t holds Minv[c][8*g8+j],  c=t>>3, g8=t&7
//   H^T matvecs read sHT[col][row] (stride 128) with STRIDED column
//   assignment m = 4*g8 + 32*i + j  ->  conflict-free float4 LDS.
// Only 24 array floats/thread -> no spills at the 64-reg cap.
// ---------------------------------------------------------------------------
__device__ __forceinline__ float sel8(const float* rm, int kj) {
    float v = rm[0];
    #pragma unroll
    for (int j = 1; j < 8; ++j) v = (j == kj) ? rm[j] : v;
    return v;
}

__global__ __launch_bounds__(512, 2)
void solver_kernel(const float* __restrict__ out3, float* __restrict__ xs)
{
    extern __shared__ __align__(16) float smdyn[];
    float* sHT = smdyn;              // 64 * 128  : H^T, persistent
    float* sLT = sHT + 64 * 128;     // 64 * LTS  : L^T (Cholesky factor)

    __shared__ __align__(16) float spiv[2 * 64];
    __shared__ __align__(16) float sxbar[64];
    __shared__ __align__(16) float stv[64];
    __shared__ __align__(16) float slam[128];
    __shared__ __align__(16) float sb[128];
    __shared__ __align__(16) float sq[64];
    __shared__ __align__(16) float sv[64];
    __shared__ __align__(16) float sw[128];
    __shared__ float spart[16];
    __shared__ float s_scal, s_tau;

    const int t    = threadIdx.x;
    const int lane = t & 31;
    const int warp = t >> 5;
    const int r    = t >> 2;   // 0..127
    const int h4   = t & 3;
    const int c    = t >> 3;   // 0..63
    const int g8   = t & 7;

    const float* row = out3 + (size_t)blockIdx.x * N_OUT;
    const unsigned FULL = 0xffffffffu;

    // ---------------- Load H row slices (coalesced float4) ----------------
    float rHr[16];
    {
        const float4* base = (const float4*)(row + HOFF + r * 64 + 16 * h4);
        float4 v0 = base[0], v1 = base[1], v2 = base[2], v3 = base[3];
        rHr[0]=v0.x;  rHr[1]=v0.y;  rHr[2]=v0.z;  rHr[3]=v0.w;
        rHr[4]=v1.x;  rHr[5]=v1.y;  rHr[6]=v1.z;  rHr[7]=v1.w;
        rHr[8]=v2.x;  rHr[9]=v2.y;  rHr[10]=v2.z; rHr[11]=v2.w;
        rHr[12]=v3.x; rHr[13]=v3.y; rHr[14]=v3.z; rHr[15]=v3.w;
    }
    // ---------------- Scatter to sHT (transposed, one-time) ----------------
    {
        float* dst = sHT + (16 * h4) * 128 + r;
        dst[0*128]=rHr[0];   dst[1*128]=rHr[1];   dst[2*128]=rHr[2];
        dst[3*128]=rHr[3];   dst[4*128]=rHr[4];   dst[5*128]=rHr[5];
        dst[6*128]=rHr[6];   dst[7*128]=rHr[7];   dst[8*128]=rHr[8];
        dst[9*128]=rHr[9];   dst[10*128]=rHr[10]; dst[11*128]=rHr[11];
        dst[12*128]=rHr[12]; dst[13*128]=rHr[13]; dst[14*128]=rHr[14];
        dst[15*128]=rHr[15];
    }

    if (t < 64)       sq[t] = row[N_P + t];
    else if (t < 192) sb[t - 64] = row[HOFF + N_HMAT + (t - 64)];
    else if (t < 256) sv[t - 192] = 0.125f;
    __syncthreads();

    // ======================= Power iteration ==============================
    for (int pit = 0; pit < 10; ++pit) {
        {   // w = H v   (r, h4)
            const float4* x4 = (const float4*)(sv + 16 * h4);
            float4 x0 = x4[0], x1 = x4[1], x2 = x4[2], x3 = x4[3];
            float a0=0.f, a1=0.f, a2=0.f, a3=0.f;
            a0 = fmaf(rHr[0],  x0.x, a0); a1 = fmaf(rHr[1],  x0.y, a1);
            a2 = fmaf(rHr[2],  x0.z, a2); a3 = fmaf(rHr[3],  x0.w, a3);
            a0 = fmaf(rHr[4],  x1.x, a0); a1 = fmaf(rHr[5],  x1.y, a1);
            a2 = fmaf(rHr[6],  x1.z, a2); a3 = fmaf(rHr[7],  x1.w, a3);
            a0 = fmaf(rHr[8],  x2.x, a0); a1 = fmaf(rHr[9],  x2.y, a1);
            a2 = fmaf(rHr[10], x2.z, a2); a3 = fmaf(rHr[11], x2.w, a3);
            a0 = fmaf(rHr[12], x3.x, a0); a1 = fmaf(rHr[13], x3.y, a1);
            a2 = fmaf(rHr[14], x3.z, a2); a3 = fmaf(rHr[15], x3.w, a3);
            float s = (a0 + a1) + (a2 + a3);
            s += __shfl_xor_sync(FULL, s, 1);
            s += __shfl_xor_sync(FULL, s, 2);
            if (h4 == 0) sw[r] = s;
        }
        __syncthreads();
        {   // p = (H^T w)[c]   (c, g8) — strided columns m = 4*g8 + 32*i + j
            float a0=0.f, a1=0.f, a2=0.f, a3=0.f;
            #pragma unroll
            for (int i = 0; i < 4; ++i) {
                float4 h = *(const float4*)&sHT[c * 128 + 4 * g8 + 32 * i];
                float4 w = *(const float4*)&sw[4 * g8 + 32 * i];
                a0 = fmaf(h.x, w.x, a0);
                a1 = fmaf(h.y, w.y, a1);
                a2 = fmaf(h.z, w.z, a2);
                a3 = fmaf(h.w, w.w, a3);
            }
            float p = (a0 + a1) + (a2 + a3);
            p += __shfl_xor_sync(FULL, p, 1);
            p += __shfl_xor_sync(FULL, p, 2);
            p += __shfl_xor_sync(FULL, p, 4);
            float pp = (g8 == 0) ? p * p : 0.f;
            #pragma unroll
            for (int off = 16; off >= 1; off >>= 1)
                pp += __shfl_xor_sync(FULL, pp, off);
            if (lane == 0) spart[warp] = pp;
            __syncthreads();
            if (t == 0) {
                float sm = 0.f;
                #pragma unroll
                for (int i = 0; i < 16; ++i) sm += spart[i];
                s_scal = sqrtf(sm) + 1e-12f;
            }
            __syncthreads();
            if (g8 == 0) sv[c] = p / s_scal;
        }
        __syncthreads();
    }

    // ---- tau = 0.9 / (||H v|| + 1e-6) ----
    {
        const float4* x4 = (const float4*)(sv + 16 * h4);
        float4 x0 = x4[0], x1 = x4[1], x2 = x4[2], x3 = x4[3];
        float a0=0.f, a1=0.f, a2=0.f, a3=0.f;
        a0 = fmaf(rHr[0],  x0.x, a0); a1 = fmaf(rHr[1],  x0.y, a1);
        a2 = fmaf(rHr[2],  x0.z, a2); a3 = fmaf(rHr[3],  x0.w, a3);
        a0 = fmaf(rHr[4],  x1.x, a0); a1 = fmaf(rHr[5],  x1.y, a1);
        a2 = fmaf(rHr[6],  x1.z, a2); a3 = fmaf(rHr[7],  x1.w, a3);
        a0 = fmaf(rHr[8],  x2.x, a0); a1 = fmaf(rHr[9],  x2.y, a1);
        a2 = fmaf(rHr[10], x2.z, a2); a3 = fmaf(rHr[11], x2.w, a3);
        a0 = fmaf(rHr[12], x3.x, a0); a1 = fmaf(rHr[13], x3.y, a1);
        a2 = fmaf(rHr[14], x3.z, a2); a3 = fmaf(rHr[15], x3.w, a3);
        float s = (a0 + a1) + (a2 + a3);
        s += __shfl_xor_sync(FULL, s, 1);
        s += __shfl_xor_sync(FULL, s, 2);
        float pp = (h4 == 0) ? s * s : 0.f;
        #pragma unroll
        for (int off = 16; off >= 1; off >>= 1)
            pp += __shfl_xor_sync(FULL, pp, off);
        if (lane == 0) spart[warp] = pp;
        __syncthreads();
        if (t == 0) {
            float sm = 0.f;
            #pragma unroll
            for (int i = 0; i < 16; ++i) sm += spart[i];
            s_tau = 0.9f / (sqrtf(sm) + 1e-6f);
        }
    }

    // ============ Build L^T in sLT (sLT[col*LTS + row]) ====================
    __syncthreads();
    for (int idx = t; idx < 64 * LTS; idx += 512) sLT[idx] = 0.f;
    __syncthreads();
    for (int idx = t; idx < N_P; idx += 512) {
        float p = row[idx];
        int rr = (int)((sqrtf(8.f * (float)idx + 1.f) - 1.f) * 0.5f);
        while ((rr * (rr + 1)) / 2 > idx) --rr;
        while (((rr + 1) * (rr + 2)) / 2 <= idx) ++rr;
        int cc = idx - (rr * (rr + 1)) / 2;
        float val;
        if (cc == rr) {
            float sp = fmaxf(p, 0.f) + log1pf(expf(-fabsf(p)));
            val = 0.1f + sp;
        } else {
            val = p;
        }
        sLT[cc * LTS + rr] = val;
    }
    __syncthreads();
    const float tau = s_tau;
    const float sig = tau;

    // ============ rM = I + tau*(L L^T) slice (c, g8) =======================
    float rM[8] = {0.f, 0.f, 0.f, 0.f, 0.f, 0.f, 0.f, 0.f};
    for (int k = 0; k < 64; ++k) {
        float a = sLT[k * LTS + c];
        float4 b0 = *(const float4*)&sLT[k * LTS + 8 * g8];
        float4 b1 = *(const float4*)&sLT[k * LTS + 8 * g8 + 4];
        rM[0] = fmaf(a, b0.x, rM[0]);
        rM[1] = fmaf(a, b0.y, rM[1]);
        rM[2] = fmaf(a, b0.z, rM[2]);
        rM[3] = fmaf(a, b0.w, rM[3]);
        rM[4] = fmaf(a, b1.x, rM[4]);
        rM[5] = fmaf(a, b1.y, rM[5]);
        rM[6] = fmaf(a, b1.z, rM[6]);
        rM[7] = fmaf(a, b1.w, rM[7]);
    }
    rM[0] = tau * rM[0] + ((8 * g8 + 0 == c) ? 1.f : 0.f);
    rM[1] = tau * rM[1] + ((8 * g8 + 1 == c) ? 1.f : 0.f);
    rM[2] = tau * rM[2] + ((8 * g8 + 2 == c) ? 1.f : 0.f);
    rM[3] = tau * rM[3] + ((8 * g8 + 3 == c) ? 1.f : 0.f);
    rM[4] = tau * rM[4] + ((8 * g8 + 4 == c) ? 1.f : 0.f);
    rM[5] = tau * rM[5] + ((8 * g8 + 5 == c) ? 1.f : 0.f);
    rM[6] = tau * rM[6] + ((8 * g8 + 6 == c) ? 1.f : 0.f);
    rM[7] = tau * rM[7] + ((8 * g8 + 7 == c) ? 1.f : 0.f);
    __syncthreads();

    // ============ Gauss-Jordan inverse (1 barrier per pivot) ===============
    for (int k = 0; k < 64; ++k) {
        const int kg = k >> 3, kj = k & 7;
        float* buf = spiv + (k & 1) * 64;
        // One unconditional shuffle: pivot value for row k, elim factor else.
        float praw = __shfl_sync(FULL, sel8(rM, kj), (lane & ~7) | kg);
        if (c == k) {
            float pinv = 1.f / praw;
            rM[0] = ((g8 == kg) && (0 == kj)) ? pinv : rM[0] * pinv;
            rM[1] = ((g8 == kg) && (1 == kj)) ? pinv : rM[1] * pinv;
            rM[2] = ((g8 == kg) && (2 == kj)) ? pinv : rM[2] * pinv;
            rM[3] = ((g8 == kg) && (3 == kj)) ? pinv : rM[3] * pinv;
            rM[4] = ((g8 == kg) && (4 == kj)) ? pinv : rM[4] * pinv;
            rM[5] = ((g8 == kg) && (5 == kj)) ? pinv : rM[5] * pinv;
            rM[6] = ((g8 == kg) && (6 == kj)) ? pinv : rM[6] * pinv;
            rM[7] = ((g8 == kg) && (7 == kj)) ? pinv : rM[7] * pinv;
            *(float4*)&buf[8 * g8 + 0] = make_float4(rM[0], rM[1], rM[2], rM[3]);
            *(float4*)&buf[8 * g8 + 4] = make_float4(rM[4], rM[5], rM[6], rM[7]);
        }
        __syncthreads();
        if (c != k) {
            const float f = praw;
            float4 p0 = *(const float4*)&buf[8 * g8 + 0];
            float4 p1 = *(const float4*)&buf[8 * g8 + 4];
            float u0 = fmaf(-f, p0.x, rM[0]);
            float u1 = fmaf(-f, p0.y, rM[1]);
            float u2 = fmaf(-f, p0.z, rM[2]);
            float u3 = fmaf(-f, p0.w, rM[3]);
            float u4 = fmaf(-f, p1.x, rM[4]);
            float u5 = fmaf(-f, p1.y, rM[5]);
            float u6 = fmaf(-f, p1.z, rM[6]);
            float u7 = fmaf(-f, p1.w, rM[7]);
            if (g8 == kg) {
                float pvk = (kj == 0) ? p0.x : (kj == 1) ? p0.y : (kj == 2) ? p0.z :
                            (kj == 3) ? p0.w : (kj == 4) ? p1.x : (kj == 5) ? p1.y :
                            (kj == 6) ? p1.z : p1.w;
                float colv = -f * pvk;
                u0 = (kj == 0) ? colv : u0;
                u1 = (kj == 1) ? colv : u1;
                u2 = (kj == 2) ? colv : u2;
                u3 = (kj == 3) ? colv : u3;
                u4 = (kj == 4) ? colv : u4;
                u5 = (kj == 5) ? colv : u5;
                u6 = (kj == 6) ? colv : u6;
                u7 = (kj == 7) ? colv : u7;
            }
            rM[0]=u0; rM[1]=u1; rM[2]=u2; rM[3]=u3;
            rM[4]=u4; rM[5]=u5; rM[6]=u6; rM[7]=u7;
        }
    }
    __syncthreads();

    // ======================= QP iterations ================================
    if (t < 64)       { sxbar[t] = 0.f; stv[t] = 0.f; }
    else if (t < 192) slam[t - 64] = 0.f;
    float xp = 0.f;
    __syncthreads();

    for (int it = 0; it < QP_ITER; ++it) {
        {   // lam = relu(lam - sig*(H xbar + b))   (r, h4)
            const float4* x4 = (const float4*)(sxbar + 16 * h4);
            float4 x0 = x4[0], x1 = x4[1], x2 = x4[2], x3 = x4[3];
            float a0=0.f, a1=0.f, a2=0.f, a3=0.f;
            a0 = fmaf(rHr[0],  x0.x, a0); a1 = fmaf(rHr[1],  x0.y, a1);
            a2 = fmaf(rHr[2],  x0.z, a2); a3 = fmaf(rHr[3],  x0.w, a3);
            a0 = fmaf(rHr[4],  x1.x, a0); a1 = fmaf(rHr[5],  x1.y, a1);
            a2 = fmaf(rHr[6],  x1.z, a2); a3 = fmaf(rHr[7],  x1.w, a3);
            a0 = fmaf(rHr[8],  x2.x, a0); a1 = fmaf(rHr[9],  x2.y, a1);
            a2 = fmaf(rHr[10], x2.z, a2); a3 = fmaf(rHr[11], x2.w, a3);
            a0 = fmaf(rHr[12], x3.x, a0); a1 = fmaf(rHr[13], x3.y, a1);
            a2 = fmaf(rHr[14], x3.z, a2); a3 = fmaf(rHr[15], x3.w, a3);
            float s = (a0 + a1) + (a2 + a3);
            s += __shfl_xor_sync(FULL, s, 1);
            s += __shfl_xor_sync(FULL, s, 2);
            if (h4 == 0) slam[r] = fmaxf(0.f, slam[r] - sig * (s + sb[r]));
        }
        __syncthreads();
        {   // tvec = xp + tau*(H^T lam - q)   (c, g8) — strided columns
            float a0=0.f, a1=0.f, a2=0.f, a3=0.f;
            #pragma unroll
            for (int i = 0; i < 4; ++i) {
                float4 h = *(const float4*)&sHT[c * 128 + 4 * g8 + 32 * i];
                float4 l = *(const float4*)&slam[4 * g8 + 32 * i];
                a0 = fmaf(h.x, l.x, a0);
                a1 = fmaf(h.y, l.y, a1);
                a2 = fmaf(h.z, l.z, a2);
                a3 = fmaf(h.w, l.w, a3);
            }
            float p = (a0 + a1) + (a2 + a3);
            p += __shfl_xor_sync(FULL, p, 1);
            p += __shfl_xor_sync(FULL, p, 2);
            p += __shfl_xor_sync(FULL, p, 4);
            if (g8 == 0) stv[c] = xp + tau * (p - sq[c]);
        }
        __syncthreads();
        {   // xn = Minv tvec ; xbar = 2 xn - xp ; xp = xn   (c, g8)
            float4 t0 = *(const float4*)&stv[8 * g8];
            float4 t1 = *(const float4*)&stv[8 * g8 + 4];
            float a0=0.f, a1=0.f, a2=0.f, a3=0.f;
            a0 = fmaf(rM[0], t0.x, a0); a1 = fmaf(rM[1], t0.y, a1);
            a2 = fmaf(rM[2], t0.z, a2); a3 = fmaf(rM[3], t0.w, a3);
            a0 = fmaf(rM[4], t1.x, a0); a1 = fmaf(rM[5], t1.y, a1);
            a2 = fmaf(rM[6], t1.z, a2); a3 = fmaf(rM[7], t1.w, a3);
            float p = (a0 + a1) + (a2 + a3);
            p += __shfl_xor_sync(FULL, p, 1);
            p += __shfl_xor_sync(FULL, p, 2);
            p += __shfl_xor_sync(FULL, p, 4);
            if (g8 == 0) {
                sxbar[c] = 2.f * p - xp;
                xp = p;
            }
        }
        __syncthreads();
    }

    if (g8 == 0) xs[(size_t)blockIdx.x * N_QP + c] = xp;
}

// ---------------------------------------------------------------------------
// Launch
// ---------------------------------------------------------------------------
extern "C" void kernel_launch(void* const* d_in, const int* in_sizes, int n_in,
                              void* d_out, int out_size)
{
    const float* x  = (const float*)d_in[0];
    const float* W1 = (const float*)d_in[1];
    const float* b1 = (const float*)d_in[2];
    const float* W2 = (const float*)d_in[3];
    const float* b2 = (const float*)d_in[4];
    const float* W3 = (const float*)d_in[5];
    const float* b3 = (const float*)d_in[6];
    float* out = (float*)d_out;

    float *p_h1, *p_h2, *p_out3;
    cudaGetSymbolAddress((void**)&p_h1, g_h1);
    cudaGetSymbolAddress((void**)&p_h2, g_h2);
    cudaGetSymbolAddress((void**)&p_out3, g_out3);

    {
        dim3 grid(HIDDEN / 64, BATCH / 64);
        sgemm_bias<true><<<grid, 256>>>(x, W1, b1, p_h1, BATCH, HIDDEN, INPUT_SIZE);
    }
    {
        dim3 grid(HIDDEN / 64, BATCH / 64);
        sgemm_bias<true><<<grid, 256>>>(p_h1, W2, b2, p_h2, BATCH, HIDDEN, HIDDEN);
    }
    {
        dim3 grid((N_OUT + 63) / 64, BATCH / 64);
        sgemm_bias<false><<<grid, 256>>>(p_h2, W3, b3, p_out3, BATCH, N_OUT, HIDDEN);
    }
    {
        const size_t dyn_bytes = (size_t)SOLVER_DYN_FLOATS * sizeof(float);
        cudaFuncSetAttribute(solver_kernel,
                             cudaFuncAttributeMaxDynamicSharedMemorySize,
                             (int)dyn_bytes);
        solver_kernel<<<BATCH, 512, dyn_bytes>>>(p_out3, out);
    }
}